// round 10
// baseline (speedup 1.0000x reference)
#include <cuda_runtime.h>
#include <math.h>

#define BB 4
#define CC 64
#define LL 4096
#define CQ 16
#define NH 4
#define NBK 32
#define NITEMS (BB * NH * NBK * 2)   // 1024 work items: (b,h,bucket,q-half)

typedef unsigned long long ull;

// ---------------- scratch (device globals; no allocation allowed) ----------------
__device__ float g_qT[BB * LL * CQ];                 // (b, l, cq)
__device__ float g_kT[BB * LL * CQ];                 // (b, l, cq)
__device__ float g_vT[BB * LL * CC];                 // (b, l, c)
__device__ int   g_sidx[BB * NH * LL];               // sorted member lists per (b,h)
__device__ int   g_boff[BB * NH * (NBK + 1)];        // bucket offsets per (b,h)
__device__ float g_acc[BB * LL * CC];                // hash-summed attention output (b,l,c)
__device__ float g_part[256 * CC];                   // BN partial sums
__device__ float g_psq[256 * CC];                    // BN partial sum of squares
__device__ float g_stats[2 * CC];                    // per-channel scale / shift
__device__ int   g_work;                             // dynamic work counter

// ---------------- packed f32x2 helpers ----------------
__device__ __forceinline__ ull pk2(float x) {
    ull r; asm("mov.b64 %0, {%1, %1};" : "=l"(r) : "f"(x)); return r;
}
__device__ __forceinline__ ull pk(float lo, float hi) {
    ull r; asm("mov.b64 %0, {%1, %2};" : "=l"(r) : "f"(lo), "f"(hi)); return r;
}
__device__ __forceinline__ float2 upk(ull a) {
    float2 f; asm("mov.b64 {%0, %1}, %2;" : "=f"(f.x), "=f"(f.y) : "l"(a)); return f;
}
__device__ __forceinline__ ull ff2(ull a, ull b, ull c) {
    ull d; asm("fma.rn.f32x2 %0, %1, %2, %3;" : "=l"(d) : "l"(a), "l"(b), "l"(c)); return d;
}
__device__ __forceinline__ ull mul2(ull a, ull b) {
    ull d; asm("mul.rn.f32x2 %0, %1, %2;" : "=l"(d) : "l"(a), "l"(b)); return d;
}

// ---------------- K1: q/k/v 1x1 convs, split by output pass (+ zero g_acc) ----------------
// grid (LL/128, BB, 6), block 128
__global__ void __launch_bounds__(128) k_qkv(
    const float* __restrict__ x,
    const float* __restrict__ Wq, const float* __restrict__ bq,
    const float* __restrict__ Wk, const float* __restrict__ bk,
    const float* __restrict__ Wv, const float* __restrict__ bv)
{
    __shared__ float WS[CQ * CC];
    __shared__ float bS[CQ];
    __shared__ float outS[128 * 17];

    const int t = threadIdx.x;
    const int l0 = blockIdx.x * 128;
    const int b  = blockIdx.y;
    const int pass = blockIdx.z;

    // zero the attention accumulator: 512 blocks (pass 2..5) x 128 thr x 4 float4
    // = 512 * 512 float4 = 4 MB = BB*LL*CC floats exactly.
    if (pass >= 2) {
        int zid = ((pass - 2) * BB + b) * gridDim.x + blockIdx.x;  // 0..511
        float4* zp = (float4*)g_acc + (size_t)zid * 512 + t;
        const float4 z = make_float4(0.f, 0.f, 0.f, 0.f);
        #pragma unroll
        for (int i = 0; i < 4; i++) zp[i * 128] = z;
    }

    const float* Wsrc; const float* bsrc;
    if (pass == 0)      { Wsrc = Wq; bsrc = bq; }
    else if (pass == 1) { Wsrc = Wk; bsrc = bk; }
    else                { Wsrc = Wv + (pass - 2) * CQ * CC; bsrc = bv + (pass - 2) * CQ; }

    for (int e = t; e < CQ * CC; e += 128) WS[e] = Wsrc[e];
    if (t < CQ) bS[t] = bsrc[t];
    __syncthreads();

    const float* xb = x + (size_t)b * CC * LL + l0 + t;

    float r[16];
    #pragma unroll
    for (int o = 0; o < 16; o++) r[o] = bS[o];

    for (int c = 0; c < CC; c++) {
        float xv = __ldg(xb + (size_t)c * LL);
        #pragma unroll
        for (int o = 0; o < 16; o++) r[o] += WS[o * CC + c] * xv;
    }

    #pragma unroll
    for (int o = 0; o < 16; o++) outS[t * 17 + o] = r[o];
    __syncthreads();

    if (pass == 0) {
        float* dst = g_qT + ((size_t)b * LL + l0) * CQ;
        for (int e = t; e < 128 * 16; e += 128) dst[e] = outS[(e >> 4) * 17 + (e & 15)];
    } else if (pass == 1) {
        float* dst = g_kT + ((size_t)b * LL + l0) * CQ;
        for (int e = t; e < 128 * 16; e += 128) dst[e] = outS[(e >> 4) * 17 + (e & 15)];
    } else {
        float* dst = g_vT + ((size_t)b * LL + l0) * CC + (pass - 2) * 16;
        for (int e = t; e < 128 * 16; e += 128) {
            int p = e >> 4, o = e & 15;
            dst[(size_t)p * CC + o] = outS[p * 17 + o];
        }
    }
}

// ---------------- K2: deterministic stable counting sort per (b,h) ----------------
__global__ void __launch_bounds__(256) k_sort(const int* __restrict__ hash_idx)
{
    __shared__ int cnt[256 * 33];
    __shared__ int tot[NBK];
    __shared__ int bbase[NBK];

    const int t  = threadIdx.x;
    const int bh = blockIdx.x;
    if (bh == 0 && t == 0) g_work = 0;   // reset attention work queue each launch
    const int* hp = hash_idx + (size_t)bh * LL;

    #pragma unroll
    for (int u = 0; u < 33; u++) cnt[t * 33 + u] = 0;

    const int l0 = t * 16;
    int loc[16];
    #pragma unroll
    for (int i = 0; i < 16; i++) {
        int bu = hp[l0 + i];
        loc[i] = bu;
        cnt[t * 33 + bu]++;
    }
    __syncthreads();

    if (t < NBK) {
        int run = 0;
        for (int j = 0; j < 256; j++) {
            int v = cnt[j * 33 + t];
            cnt[j * 33 + t] = run;
            run += v;
        }
        tot[t] = run;
    }
    __syncthreads();

    if (t == 0) {
        int running = 0;
        for (int u = 0; u < NBK; u++) {
            bbase[u] = running;
            g_boff[bh * (NBK + 1) + u] = running;
            running += tot[u];
        }
        g_boff[bh * (NBK + 1) + NBK] = running;
    }
    __syncthreads();

    int* sp = g_sidx + (size_t)bh * LL;
    #pragma unroll
    for (int i = 0; i < 16; i++) {
        int bu = loc[i];
        int pos = bbase[bu] + cnt[t * 33 + bu];
        cnt[t * 33 + bu]++;
        sp[pos] = l0 + i;
    }
}

// ---------------- K3: persistent flash attention, warp-local softmax ----------------
// 444 persistent blocks of 256 threads pull (b,h,bucket,q-half) items.
// GEMM1: warp w owns query rows w*8..w*8+7 over all 64 keys (lane -> k=2l,2l+1);
// softmax max/sum via warp butterflies, m/l carried in registers.
// PV: warp w owns channels w*8..w*8+8, lanes own queries. 3 barriers per chunk.
// Epilogue: RED.ADD of 0.25*out/l into g_acc (b,l,c).
__global__ void __launch_bounds__(256, 3) k_attn()
{
    __shared__ __align__(16) ull   Qd[CQ * 68];   // [c][q] value duplicated into f32x2
    __shared__ __align__(16) float Ks[CQ * 68];   // [c][k]
    __shared__ __align__(16) float Vs[64 * 68];   // [k][c]
    __shared__ __align__(16) float S[64 * 68];    // [q][k] probabilities
    __shared__ float corrS[64], lS[64];
    __shared__ int itemS;

    const int t = threadIdx.x, w = t >> 5, lane = t & 31;

    for (;;) {
        if (t == 0) itemS = atomicAdd(&g_work, 1);
        __syncthreads();
        const int item = itemS;
        if (item >= NITEMS) break;

        const int qh = item & 1;
        const int bu = (item >> 1) & (NBK - 1);
        const int bh = item >> 6;
        const int b  = bh >> 2;

        const int base = g_boff[bh * (NBK + 1) + bu];
        const int n    = g_boff[bh * (NBK + 1) + bu + 1] - base;
        const int h0   = qh * ((n + 1) >> 1);
        const int nqt  = (qh == 0) ? ((n + 1) >> 1) : (n - ((n + 1) >> 1));
        if (n <= 0 || nqt <= 0) { __syncthreads(); continue; }

        const int*   sp  = g_sidx + (size_t)bh * LL + base;
        const float* kTb = g_kT + (size_t)b * LL * CQ;
        const float* qTb = g_qT + (size_t)b * LL * CQ;
        const float* vTb = g_vT + (size_t)b * LL * CC;
        float*       ob  = g_acc + (size_t)b * LL * CC;

        for (int q0s = h0; q0s < h0 + nqt; q0s += 64) {
            const int nq = min(64, h0 + nqt - q0s);

            __syncthreads();  // prior item/subtile smem readers done
            // stage Q duplicated [c][q]
            if (t < 64) {
                int qp = __ldg(&sp[q0s + min(t, nq - 1)]);
                const float4* qr = (const float4*)(qTb + (size_t)qp * CQ);
                #pragma unroll
                for (int c4 = 0; c4 < 4; c4++) {
                    float4 v = __ldg(qr + c4);
                    Qd[(c4 * 4 + 0) * 68 + t] = pk2(v.x);
                    Qd[(c4 * 4 + 1) * 68 + t] = pk2(v.y);
                    Qd[(c4 * 4 + 2) * 68 + t] = pk2(v.z);
                    Qd[(c4 * 4 + 3) * 68 + t] = pk2(v.w);
                }
            }

            float m0[8], l0[8];
            #pragma unroll
            for (int q = 0; q < 8; q++) { m0[q] = -3.0e38f; l0[q] = 0.f; }
            ull A0[4] = {0, 0, 0, 0}, A1[4] = {0, 0, 0, 0};

            for (int k0 = 0; k0 < n; k0 += 64) {
                const int tn = min(64, n - k0);
                __syncthreads();  // Qd staged (1st iter) / prev PV readers done

                // stage K [c][k]
                if (t < 64) {
                    int kp = __ldg(&sp[k0 + min(t, tn - 1)]);
                    const float4* kr = (const float4*)(kTb + (size_t)kp * CQ);
                    #pragma unroll
                    for (int c4 = 0; c4 < 4; c4++) {
                        float4 v = __ldg(kr + c4);
                        Ks[(c4 * 4 + 0) * 68 + t] = v.x;
                        Ks[(c4 * 4 + 1) * 68 + t] = v.y;
                        Ks[(c4 * 4 + 2) * 68 + t] = v.z;
                        Ks[(c4 * 4 + 3) * 68 + t] = v.w;
                    }
                }
                // stage V [k][c]
                #pragma unroll
                for (int it = 0; it < 4; it++) {
                    int idx = t + it * 256;
                    int kk = idx >> 4, c4 = idx & 15;
                    int kp = __ldg(&sp[k0 + min(kk, tn - 1)]);
                    float4 v = __ldg((const float4*)(vTb + (size_t)kp * CC) + c4);
                    *(float4*)&Vs[kk * 68 + c4 * 4] = v;
                }
                __syncthreads();  // K/V staged

                // GEMM1 + warp-local online softmax
                {
                    ull s2[8] = {0, 0, 0, 0, 0, 0, 0, 0};
                    #pragma unroll
                    for (int c = 0; c < CQ; c++) {
                        ull kk2 = *(const ull*)&Ks[c * 68 + 2 * lane];
                        ulonglong2 qa = *(const ulonglong2*)&Qd[c * 68 + w * 8];
                        ulonglong2 qb = *(const ulonglong2*)&Qd[c * 68 + w * 8 + 2];
                        ulonglong2 qc = *(const ulonglong2*)&Qd[c * 68 + w * 8 + 4];
                        ulonglong2 qd = *(const ulonglong2*)&Qd[c * 68 + w * 8 + 6];
                        s2[0] = ff2(kk2, qa.x, s2[0]); s2[1] = ff2(kk2, qa.y, s2[1]);
                        s2[2] = ff2(kk2, qb.x, s2[2]); s2[3] = ff2(kk2, qb.y, s2[3]);
                        s2[4] = ff2(kk2, qc.x, s2[4]); s2[5] = ff2(kk2, qc.y, s2[5]);
                        s2[6] = ff2(kk2, qd.x, s2[6]); s2[7] = ff2(kk2, qd.y, s2[7]);
                    }
                    // warp max per q
                    float sr[8];
                    #pragma unroll
                    for (int q = 0; q < 8; q++) { float2 v = upk(s2[q]); sr[q] = fmaxf(v.x, v.y); }
                    #pragma unroll
                    for (int o = 16; o; o >>= 1) {
                        #pragma unroll
                        for (int q = 0; q < 8; q++)
                            sr[q] = fmaxf(sr[q], __shfl_xor_sync(0xffffffffu, sr[q], o));
                    }
                    float corr[8];
                    #pragma unroll
                    for (int q = 0; q < 8; q++) {
                        float mn = fmaxf(m0[q], sr[q]);
                        corr[q] = __expf(m0[q] - mn);
                        m0[q] = mn;
                    }
                    // exp + mask + write probs + warp sum
                    const bool v0 = (2 * lane     < tn);
                    const bool v1 = (2 * lane + 1 < tn);
                    float ss[8];
                    #pragma unroll
                    for (int q = 0; q < 8; q++) {
                        float2 sv = upk(s2[q]);
                        float p0 = v0 ? __expf(sv.x - m0[q]) : 0.f;
                        float p1 = v1 ? __expf(sv.y - m0[q]) : 0.f;
                        *(ull*)&S[(w * 8 + q) * 68 + 2 * lane] = pk(p0, p1);
                        ss[q] = p0 + p1;
                    }
                    #pragma unroll
                    for (int o = 16; o; o >>= 1) {
                        #pragma unroll
                        for (int q = 0; q < 8; q++)
                            ss[q] += __shfl_xor_sync(0xffffffffu, ss[q], o);
                    }
                    #pragma unroll
                    for (int q = 0; q < 8; q++) l0[q] = l0[q] * corr[q] + ss[q];
                    if (lane == 0) {
                        #pragma unroll
                        for (int q = 0; q < 8; q++) corrS[w * 8 + q] = corr[q];
                    }
                }
                __syncthreads();  // probs + corr visible

                // PV + rescale (warp owns 8 channels; lanes own queries)
                {
                    ull C0 = pk2(corrS[lane]), C1 = pk2(corrS[lane + 32]);
                    #pragma unroll
                    for (int j = 0; j < 4; j++) { A0[j] = mul2(A0[j], C0); A1[j] = mul2(A1[j], C1); }

                    const float* S0 = S + lane * 68;
                    const float* S1 = S + (lane + 32) * 68;
                    #pragma unroll 4
                    for (int k4 = 0; k4 < 16; k4++) {
                        float4 p0 = *(const float4*)(S0 + k4 * 4);
                        float4 p1 = *(const float4*)(S1 + k4 * 4);
                        const float* vr = Vs + (k4 * 4) * 68 + w * 8;
                        #pragma unroll
                        for (int u = 0; u < 4; u++) {
                            ulonglong2 va = *(const ulonglong2*)(vr);
                            ulonglong2 vb = *(const ulonglong2*)(vr + 4);
                            float p0c = (u == 0) ? p0.x : (u == 1) ? p0.y : (u == 2) ? p0.z : p0.w;
                            float p1c = (u == 0) ? p1.x : (u == 1) ? p1.y : (u == 2) ? p1.z : p1.w;
                            ull P0 = pk2(p0c), P1 = pk2(p1c);
                            A0[0] = ff2(P0, va.x, A0[0]); A0[1] = ff2(P0, va.y, A0[1]);
                            A0[2] = ff2(P0, vb.x, A0[2]); A0[3] = ff2(P0, vb.y, A0[3]);
                            A1[0] = ff2(P1, va.x, A1[0]); A1[1] = ff2(P1, va.y, A1[1]);
                            A1[2] = ff2(P1, vb.x, A1[2]); A1[3] = ff2(P1, vb.y, A1[3]);
                            vr += 68;
                        }
                    }
                }
            }

            // publish denominators from q-owner warps
            if (lane == 0) {
                #pragma unroll
                for (int q = 0; q < 8; q++) lS[w * 8 + q] = l0[q];
            }
            __syncthreads();

            // epilogue: RED 0.25*out/l into g_acc (disjoint q per item, races only across hashes)
            {
                float i0 = 0.25f / lS[lane];
                float i1 = 0.25f / lS[lane + 32];
                if (lane < nq) {
                    int qpos = __ldg(&sp[q0s + lane]);
                    float* dst = ob + (size_t)qpos * CC + w * 8;
                    #pragma unroll
                    for (int j = 0; j < 4; j++) {
                        float2 v = upk(A0[j]);
                        atomicAdd(dst + 2 * j,     v.x * i0);
                        atomicAdd(dst + 2 * j + 1, v.y * i0);
                    }
                }
                if (lane + 32 < nq) {
                    int qpos = __ldg(&sp[q0s + lane + 32]);
                    float* dst = ob + (size_t)qpos * CC + w * 8;
                    #pragma unroll
                    for (int j = 0; j < 4; j++) {
                        float2 v = upk(A1[j]);
                        atomicAdd(dst + 2 * j,     v.x * i1);
                        atomicAdd(dst + 2 * j + 1, v.y * i1);
                    }
                }
            }
        }
    }
}

// ---------------- K4: Wo conv + residual + BN partials (reads 4MB g_acc) ----------------
// grid (LL/64, BB) = 256 blocks, 256 threads: 64 pos x 64 ch tiles
__global__ void __launch_bounds__(256) k_out(
    const float* __restrict__ x,
    const float* __restrict__ Wo, const float* __restrict__ bo,
    const float* __restrict__ gamma, float* __restrict__ out)
{
    __shared__ float WoS[CC * 65];
    __shared__ __align__(16) float attnS[CC * 68];   // [c][pos]

    const int t  = threadIdx.x;
    const int l0 = blockIdx.x * 64;
    const int b  = blockIdx.y;

    for (int e = t; e < CC * CC; e += 256) WoS[(e >> 6) * 65 + (e & 63)] = Wo[e];

    const float* ab = g_acc + ((size_t)b * LL + l0) * CC;
    for (int e = t; e < 64 * CC; e += 256) {
        int pos = e >> 6, c = e & 63;
        attnS[c * 68 + pos] = ab[e];
    }
    __syncthreads();

    const int cgrp = t >> 4, pgrp = t & 15, c0 = cgrp * 4;
    float acc[4][4];
    #pragma unroll
    for (int i = 0; i < 4; i++) {
        float bi = __ldg(bo + c0 + i);
        #pragma unroll
        for (int j = 0; j < 4; j++) acc[i][j] = bi;
    }

    for (int cp = 0; cp < CC; cp++) {
        float4 av = *(const float4*)&attnS[cp * 68 + pgrp * 4];
        #pragma unroll
        for (int i = 0; i < 4; i++) {
            float w = WoS[(c0 + i) * 65 + cp];
            acc[i][0] += w * av.x; acc[i][1] += w * av.y;
            acc[i][2] += w * av.z; acc[i][3] += w * av.w;
        }
    }

    const float g = __ldg(gamma);
    const int blk = b * gridDim.x + blockIdx.x;   // 0..255

    #pragma unroll
    for (int i = 0; i < 4; i++) {
        int c = c0 + i;
        size_t gbase = ((size_t)b * CC + c) * LL + l0 + pgrp * 4;
        float4 xv = *(const float4*)(x + gbase);
        float4 y;
        y.x = g * acc[i][0] + xv.x;
        y.y = g * acc[i][1] + xv.y;
        y.z = g * acc[i][2] + xv.z;
        y.w = g * acc[i][3] + xv.w;
        *(float4*)(out + gbase) = y;

        float s1 = y.x + y.y + y.z + y.w;
        float s2 = y.x * y.x + y.y * y.y + y.z * y.z + y.w * y.w;
        #pragma unroll
        for (int o = 8; o; o >>= 1) {
            s1 += __shfl_xor_sync(0xffffffffu, s1, o);
            s2 += __shfl_xor_sync(0xffffffffu, s2, o);
        }
        if (pgrp == 0) { g_part[blk * CC + c] = s1; g_psq[blk * CC + c] = s2; }
    }
}

// ---------------- K5: BN stats reduce (256 threads) ----------------
__global__ void __launch_bounds__(256) k_stats(const float* __restrict__ bn_w, const float* __restrict__ bn_b)
{
    __shared__ double sd1[256], sd2[256];
    const int t = threadIdx.x;
    const int c = t & 63, qr = t >> 6;
    double s1 = 0.0, s2 = 0.0;
    for (int i = qr * 64; i < qr * 64 + 64; i++) {
        s1 += g_part[i * CC + c];
        s2 += g_psq[i * CC + c];
    }
    sd1[t] = s1; sd2[t] = s2;
    __syncthreads();
    if (t < 64) {
        double t1 = sd1[t] + sd1[64 + t] + sd1[128 + t] + sd1[192 + t];
        double t2 = sd2[t] + sd2[64 + t] + sd2[128 + t] + sd2[192 + t];
        const double n = (double)BB * (double)LL;
        double mean = t1 / n;
        double var  = t2 / n - mean * mean;
        double a    = (double)bn_w[t] / sqrt(var + 1e-5);
        g_stats[t]      = (float)a;
        g_stats[CC + t] = (float)((double)bn_b[t] - mean * a);
    }
}

// ---------------- K6: normalize in place ----------------
__global__ void __launch_bounds__(256) k_norm(float* __restrict__ out)
{
    int i = blockIdx.x * 256 + threadIdx.x;
    int c = (i >> 10) & 63;
    float a = g_stats[c], sh = g_stats[CC + c];
    float4* p = (float4*)out;
    float4 v = p[i];
    v.x = v.x * a + sh; v.y = v.y * a + sh;
    v.z = v.z * a + sh; v.w = v.w * a + sh;
    p[i] = v;
}

// ---------------- launch ----------------
extern "C" void kernel_launch(void* const* d_in, const int* in_sizes, int n_in,
                              void* d_out, int out_size)
{
    const float* x     = (const float*)d_in[0];
    const int*   hashi = (const int*)  d_in[1];
    const float* Wq    = (const float*)d_in[2];
    const float* bq    = (const float*)d_in[3];
    const float* Wk    = (const float*)d_in[4];
    const float* bk    = (const float*)d_in[5];
    const float* Wv    = (const float*)d_in[6];
    const float* bv    = (const float*)d_in[7];
    const float* Wo    = (const float*)d_in[8];
    const float* bo    = (const float*)d_in[9];
    const float* gamma = (const float*)d_in[10];
    const float* bn_w  = (const float*)d_in[11];
    const float* bn_b  = (const float*)d_in[12];
    float* out = (float*)d_out;

    k_qkv<<<dim3(LL / 128, BB, 6), 128>>>(x, Wq, bq, Wk, bk, Wv, bv);
    k_sort<<<BB * NH, 256>>>(hashi);
    k_attn<<<444, 256>>>();
    k_out<<<dim3(LL / 64, BB), 256>>>(x, Wo, bo, gamma, out);
    k_stats<<<1, 256>>>(bn_w, bn_b);
    k_norm<<<(BB * CC * LL / 4) / 256, 256>>>(out);
}